// round 8
// baseline (speedup 1.0000x reference)
#include <cuda_runtime.h>
#include <cuda_bf16.h>
#include <cstdint>

// Problem constants (fixed by the reference)
#define EMB    64
#define HEADS  8
#define DIMI   20
#define NQ     4116                  // DIMI + 16*16*16
#define ROWF4  1029                  // 4116 / 4
#define TABR   63                    // 2*CAP - 1
#define INVT   0.125f                // 64^-0.5

#define CONTENT_BLOCKS 8192          // HEADS*16*16*4  (h, i, j, k3 group of 4)
#define ZERO_BLOCKS    40            // 160 zero rows / 4
#define GRID_SCORES    (CONTENT_BLOCKS + ZERO_BLOCKS)
#define SPAN_F4        (4 * ROWF4)   // 4116 float4 per block

#define NTAB 116                     // 16 sa + 16 sb + 64 sd + 20 scr

// Fused kernel: each content block computes its 116 table entries from the
// raw inputs (L2-resident, ~60 KB total), then streams 4 contiguous rows
// (65.9 KB) of output. Zero blocks write 4 all-zero rows.
__global__ __launch_bounds__(256)
void scores_kernel(float* __restrict__ out,
                   const float* __restrict__ enc_cross,
                   const float* __restrict__ enc_h,
                   const float* __restrict__ enc_w,
                   const float* __restrict__ enc_d,
                   const float* __restrict__ w_cross,
                   const float* __restrict__ w_h,
                   const float* __restrict__ w_w,
                   const float* __restrict__ w_d) {
    const int b = blockIdx.x;
    const int t = threadIdx.x;

    if (b >= CONTENT_BLOCKS) {
        const int zb = b - CONTENT_BLOCKS;        // 0..39
        const int h  = zb / 5;                    // 4-row groups stay in one head
        const int q0 = (zb - h * 5) * 4;
        float4* __restrict__ dst =
            reinterpret_cast<float4*>(out + ((size_t)h * NQ + q0) * NQ);
        const float4 z = make_float4(0.f, 0.f, 0.f, 0.f);
        #pragma unroll 4
        for (int g = t; g < SPAN_F4; g += 256) dst[g] = z;
        return;
    }

    const int h  = b >> 10;
    const int i  = (b >> 6) & 15;
    const int j  = (b >> 2) & 15;
    const int kg = b & 3;                         // k3 = 4*kg + r, r = 0..3

    // Table layout (pre-shifted so the store loop does no index shifts):
    //   stab[0:16)    sa[l]      = projH[l - i + 31]          * INVT/3
    //   stab[16:32)   sb[m]      = projW[m - j + 31]          * INVT/3
    //   stab[32:96)   sd[r][n0]  = projD[n0 - (4kg+r) + 31]   * INVT/3
    //   stab[96:116)  scr[n]     = cross[h][n]                * INVT
    __shared__ float stab[NTAB];
    {
        const int warp = t >> 5;
        const int lane = t & 31;
        #pragma unroll
        for (int k = 0; k < 15; k++) {            // 15 products/warp, independent
            const int p = warp + 8 * k;           // 0..119
            if (p < NTAB) {
                const float* wv;
                const float* vv;
                float scale;
                if (p < 16) {
                    wv = w_h + h * EMB;
                    vv = enc_h + (p - i + 31) * EMB;
                    scale = INVT / 3.0f;
                } else if (p < 32) {
                    wv = w_w + h * EMB;
                    vv = enc_w + ((p - 16) - j + 31) * EMB;
                    scale = INVT / 3.0f;
                } else if (p < 96) {
                    const int idx = p - 32;
                    const int r   = idx >> 4;
                    const int n0  = idx & 15;
                    wv = w_d + h * EMB;
                    vv = enc_d + (n0 - (4 * kg + r) + 31) * EMB;
                    scale = INVT / 3.0f;
                } else {
                    wv = w_cross + h * EMB;
                    vv = enc_cross + (p - 96) * EMB;  // rows 0..19 contiguous
                    scale = INVT;
                }
                float s = wv[lane] * vv[lane] + wv[lane + 32] * vv[lane + 32];
                #pragma unroll
                for (int off = 16; off > 0; off >>= 1)
                    s += __shfl_xor_sync(0xffffffffu, s, off);
                if (lane == 0) stab[p] = s * scale;
            }
        }
    }
    __syncthreads();

    const float* sa  = &stab[0];
    const float* sb  = &stab[16];
    const float* sd  = &stab[32];     // [4][16]
    const float* scr = &stab[96];

    const int base_row = h * NQ + DIMI + i * 256 + j * 16 + 4 * kg;
    float4* __restrict__ dst = reinterpret_cast<float4*>(out + (size_t)base_row * NQ);

    #pragma unroll 4
    for (int g = t; g < SPAN_F4; g += 256) {
        const int r = g / ROWF4;          // 0..3, mulhi sequence
        const int f = g - r * ROWF4;
        float4 v;
        if (f < 5) {
            const float* c = &scr[4 * f];
            v.x = c[0]; v.y = c[1]; v.z = c[2]; v.w = c[3];
        } else {
            const int scol = 4 * f - DIMI;         // multiple of 4
            const int l  = scol >> 8;
            const int m  = (scol >> 4) & 15;
            const int n0 = scol & 15;
            const float base = sa[l] + sb[m];
            const float* d = &sd[r * 16 + n0];
            v.x = base + d[0];
            v.y = base + d[1];
            v.z = base + d[2];
            v.w = base + d[3];
        }
        dst[g] = v;
    }
}

extern "C" void kernel_launch(void* const* d_in, const int* in_sizes, int n_in,
                              void* d_out, int out_size) {
    const float* enc_cross = (const float*)d_in[0];
    const float* enc_h     = (const float*)d_in[1];
    const float* enc_w     = (const float*)d_in[2];
    const float* enc_d     = (const float*)d_in[3];
    const float* w_cross   = (const float*)d_in[4];
    const float* w_h       = (const float*)d_in[5];
    const float* w_w       = (const float*)d_in[6];
    const float* w_d       = (const float*)d_in[7];
    float* out = (float*)d_out;

    scores_kernel<<<GRID_SCORES, 256>>>(out, enc_cross, enc_h, enc_w, enc_d,
                                        w_cross, w_h, w_w, w_d);
}

// round 9
// speedup vs baseline: 1.0556x; 1.0556x over previous
#include <cuda_runtime.h>
#include <cuda_bf16.h>
#include <cstdint>

// Problem constants (fixed by the reference)
#define EMB    64
#define HEADS  8
#define DIMI   20
#define NQ     4116                  // DIMI + 16*16*16
#define ROWF4  1029                  // 4116 / 4
#define TABR   63                    // 2*CAP - 1
#define INVT   0.125f                // 64^-0.5

#define NPROJ  (3 * HEADS * TABR)    // 1512
#define NCROSS (HEADS * DIMI)        // 160
#define NITEMS (NPROJ + NCROSS)      // 1672

// Precomputed small tables (scaling folded in)
__device__ float g_projH[HEADS * TABR];   // * INVT/3
__device__ float g_projW[HEADS * TABR];
__device__ float g_projD[HEADS * TABR];
__device__ float g_cross[HEADS * DIMI];   // * INVT

// One warp per output scalar: lane c handles elements c and c+32 of the
// 64-length dot product, then butterfly-reduce. Fires the PDL trigger once
// the tables are written so the dependent scores grid can proceed.
__global__ __launch_bounds__(256)
void prep_kernel(const float* __restrict__ enc_cross,
                 const float* __restrict__ enc_h,
                 const float* __restrict__ enc_w,
                 const float* __restrict__ enc_d,
                 const float* __restrict__ w_cross,
                 const float* __restrict__ w_h,
                 const float* __restrict__ w_w,
                 const float* __restrict__ w_d) {
    const int warp = blockIdx.x * 8 + (threadIdx.x >> 5);
    const int lane = threadIdx.x & 31;

    if (warp < NITEMS) {
        const float* vec;
        const float* w;
        float scale;
        float* dst;

        if (warp < NPROJ) {
            const int axis = warp / (HEADS * TABR);
            const int rem  = warp - axis * (HEADS * TABR);
            const int h = rem / TABR, r = rem - h * TABR;
            const float* tab = (axis == 0) ? enc_h : (axis == 1) ? enc_w : enc_d;
            const float* wt  = (axis == 0) ? w_h   : (axis == 1) ? w_w   : w_d;
            float* db        = (axis == 0) ? g_projH : (axis == 1) ? g_projW : g_projD;
            vec = tab + r * EMB;
            w   = wt + h * EMB;
            scale = INVT / 3.0f;
            dst = db + h * TABR + r;
        } else {
            const int rem = warp - NPROJ;
            const int h = rem / DIMI, n = rem - h * DIMI;
            vec = enc_cross + n * EMB;
            w   = w_cross + h * EMB;
            scale = INVT;
            dst = g_cross + h * DIMI + n;
        }

        float s = w[lane] * vec[lane] + w[lane + 32] * vec[lane + 32];
        #pragma unroll
        for (int off = 16; off > 0; off >>= 1)
            s += __shfl_xor_sync(0xffffffffu, s, off);
        if (lane == 0) *dst = s * scale;
    }

#if __CUDA_ARCH__ >= 900
    cudaTriggerProgrammaticLaunchCompletion();
#endif
}

// One block per output row (h, q). 256 threads, float4 stores.
// Zero rows need no tables -> skip the grid-dependency sync and overlap
// with prep. Content rows sync before reading g_*.
__global__ __launch_bounds__(256)
void scores_kernel(float* __restrict__ out) {
    const int bid = blockIdx.x;              // h * NQ + q
    const int h = bid / NQ;
    const int q = bid - h * NQ;
    float4* __restrict__ row = reinterpret_cast<float4*>(out + (size_t)bid * NQ);
    const int t = threadIdx.x;

    if (q < DIMI) {
        const float4 z = make_float4(0.f, 0.f, 0.f, 0.f);
        for (int f = t; f < ROWF4; f += 256) row[f] = z;
        return;
    }

#if __CUDA_ARCH__ >= 900
    cudaGridDependencySynchronize();
#endif

    __shared__ float sa[16], sb[16], sc[16], scr[DIMI];
    const int srow = q - DIMI;
    const int i  = srow >> 8;
    const int j  = (srow >> 4) & 15;
    const int k3 = srow & 15;

    if (t < 16)       sa[t]        = g_projH[h * TABR + (t)        - i  + 31];
    else if (t < 32)  sb[t - 16]   = g_projW[h * TABR + (t - 16)   - j  + 31];
    else if (t < 48)  sc[t - 32]   = g_projD[h * TABR + (t - 32)   - k3 + 31];
    else if (t < 48 + DIMI) scr[t - 48] = g_cross[h * DIMI + (t - 48)];
    __syncthreads();

    for (int f = t; f < ROWF4; f += 256) {
        float4 v;
        if (f < 5) {
            v.x = scr[4 * f + 0];
            v.y = scr[4 * f + 1];
            v.z = scr[4 * f + 2];
            v.w = scr[4 * f + 3];
        } else {
            const int scol = 4 * f - DIMI;           // multiple of 4
            const int l  = scol >> 8;
            const int m  = (scol >> 4) & 15;
            const int n0 = scol & 15;                // 0,4,8,12
            const float base = sa[l] + sb[m];
            v.x = base + sc[n0 + 0];
            v.y = base + sc[n0 + 1];
            v.z = base + sc[n0 + 2];
            v.w = base + sc[n0 + 3];
        }
        row[f] = v;
    }
}

extern "C" void kernel_launch(void* const* d_in, const int* in_sizes, int n_in,
                              void* d_out, int out_size) {
    const float* enc_cross = (const float*)d_in[0];
    const float* enc_h     = (const float*)d_in[1];
    const float* enc_w     = (const float*)d_in[2];
    const float* enc_d     = (const float*)d_in[3];
    const float* w_cross   = (const float*)d_in[4];
    const float* w_h       = (const float*)d_in[5];
    const float* w_w       = (const float*)d_in[6];
    const float* w_d       = (const float*)d_in[7];
    float* out = (float*)d_out;

    prep_kernel<<<(NITEMS + 7) / 8, 256>>>(enc_cross, enc_h, enc_w, enc_d,
                                           w_cross, w_h, w_w, w_d);

    // Dependent launch with programmatic stream serialization (PDL):
    // scores blocks may launch while prep is still running; content blocks
    // gate on cudaGridDependencySynchronize().
    cudaLaunchConfig_t cfg = {};
    cfg.gridDim  = dim3(HEADS * NQ);
    cfg.blockDim = dim3(256);
    cfg.dynamicSmemBytes = 0;
    cfg.stream = 0;
    cudaLaunchAttribute attr[1];
    attr[0].id = cudaLaunchAttributeProgrammaticStreamSerialization;
    attr[0].val.programmaticStreamSerializationAllowed = 1;
    cfg.attrs = attr;
    cfg.numAttrs = 1;
    cudaLaunchKernelEx(&cfg, scores_kernel, out);
}

// round 10
// speedup vs baseline: 1.0612x; 1.0053x over previous
#include <cuda_runtime.h>
#include <cuda_bf16.h>
#include <cstdint>

// Problem constants (fixed by the reference)
#define EMB    64
#define HEADS  8
#define DIMI   20
#define NQ     4116                  // DIMI + 16*16*16
#define ROWF4  1029                  // 4116 / 4
#define TABR   63                    // 2*CAP - 1
#define INVT   0.125f                // 64^-0.5

#define NPROJ  (3 * HEADS * TABR)    // 1512
#define NCROSS (HEADS * DIMI)        // 160
#define NITEMS (NPROJ + NCROSS)      // 1672

// Precomputed small tables (scaling folded in)
__device__ float g_projH[HEADS * TABR];   // * INVT/3
__device__ float g_projW[HEADS * TABR];
__device__ float g_projD[HEADS * TABR];
__device__ float g_cross[HEADS * DIMI];   // * INVT

// One warp per output scalar: lane c handles elements c and c+32 of the
// 64-length dot product, then butterfly-reduce. Fires the PDL trigger once
// the tables are written so the dependent scores grid can proceed.
__global__ __launch_bounds__(256)
void prep_kernel(const float* __restrict__ enc_cross,
                 const float* __restrict__ enc_h,
                 const float* __restrict__ enc_w,
                 const float* __restrict__ enc_d,
                 const float* __restrict__ w_cross,
                 const float* __restrict__ w_h,
                 const float* __restrict__ w_w,
                 const float* __restrict__ w_d) {
    const int warp = blockIdx.x * 8 + (threadIdx.x >> 5);
    const int lane = threadIdx.x & 31;

    if (warp < NITEMS) {
        const float* vec;
        const float* w;
        float scale;
        float* dst;

        if (warp < NPROJ) {
            const int axis = warp / (HEADS * TABR);
            const int rem  = warp - axis * (HEADS * TABR);
            const int h = rem / TABR, r = rem - h * TABR;
            const float* tab = (axis == 0) ? enc_h : (axis == 1) ? enc_w : enc_d;
            const float* wt  = (axis == 0) ? w_h   : (axis == 1) ? w_w   : w_d;
            float* db        = (axis == 0) ? g_projH : (axis == 1) ? g_projW : g_projD;
            vec = tab + r * EMB;
            w   = wt + h * EMB;
            scale = INVT / 3.0f;
            dst = db + h * TABR + r;
        } else {
            const int rem = warp - NPROJ;
            const int h = rem / DIMI, n = rem - h * DIMI;
            vec = enc_cross + n * EMB;
            w   = w_cross + h * EMB;
            scale = INVT;
            dst = g_cross + h * DIMI + n;
        }

        float s = w[lane] * vec[lane] + w[lane + 32] * vec[lane + 32];
        #pragma unroll
        for (int off = 16; off > 0; off >>= 1)
            s += __shfl_xor_sync(0xffffffffu, s, off);
        if (lane == 0) *dst = s * scale;
    }

#if __CUDA_ARCH__ >= 900
    cudaTriggerProgrammaticLaunchCompletion();
#endif
}

// One block per output row (h, q), 256 threads.
// Content span f in [5, 1029) is exactly 1024 float4 = 4 branch-free
// iterations x 256 threads, with the D-axis values iteration-invariant.
__global__ __launch_bounds__(256)
void scores_kernel(float* __restrict__ out) {
    const int bid = blockIdx.x;              // h * NQ + q
    const int h = bid / NQ;
    const int q = bid - h * NQ;
    float4* __restrict__ row = reinterpret_cast<float4*>(out + (size_t)bid * NQ);
    const int t = threadIdx.x;

    if (q < DIMI) {
        // zero row: no tables needed, no PDL sync — overlaps with prep
        const float4 z = make_float4(0.f, 0.f, 0.f, 0.f);
        for (int f = t; f < ROWF4; f += 256) row[f] = z;
        return;
    }

#if __CUDA_ARCH__ >= 900
    cudaGridDependencySynchronize();
#endif

    __shared__ float sa[16], sb[16], sc[16], scr[DIMI];
    const int srow = q - DIMI;
    const int i  = srow >> 8;
    const int j  = (srow >> 4) & 15;
    const int k3 = srow & 15;

    if (t < 16)       sa[t]        = g_projH[h * TABR + (t)        - i  + 31];
    else if (t < 32)  sb[t - 16]   = g_projW[h * TABR + (t - 16)   - j  + 31];
    else if (t < 48)  sc[t - 32]   = g_projD[h * TABR + (t - 32)   - k3 + 31];
    else if (t < 48 + DIMI) scr[t - 48] = g_cross[h * DIMI + (t - 48)];
    __syncthreads();

    // Cross block: 5 float4s (k = 0..19), threads 0..4
    if (t < 5) {
        float4 v;
        v.x = scr[4 * t + 0];
        v.y = scr[4 * t + 1];
        v.z = scr[4 * t + 2];
        v.w = scr[4 * t + 3];
        row[t] = v;
    }

    // Content block: f = 5 + t + 256*it, it = 0..3 (exact, no tail).
    // scol = 4*f - 20 = 4*t + 1024*it  =>  n0 = (4*t) & 15 is loop-invariant.
    const int scol0 = 4 * t;
    const int n0 = scol0 & 15;
    const float c0 = sc[n0 + 0];
    const float c1 = sc[n0 + 1];
    const float c2 = sc[n0 + 2];
    const float c3 = sc[n0 + 3];

    #pragma unroll
    for (int it = 0; it < 4; it++) {
        const int scol = scol0 + 1024 * it;
        const int l = scol >> 8;
        const int m = (scol >> 4) & 15;
        const float base = sa[l] + sb[m];
        float4 v;
        v.x = base + c0;
        v.y = base + c1;
        v.z = base + c2;
        v.w = base + c3;
        row[5 + t + 256 * it] = v;
    }
}

extern "C" void kernel_launch(void* const* d_in, const int* in_sizes, int n_in,
                              void* d_out, int out_size) {
    const float* enc_cross = (const float*)d_in[0];
    const float* enc_h     = (const float*)d_in[1];
    const float* enc_w     = (const float*)d_in[2];
    const float* enc_d     = (const float*)d_in[3];
    const float* w_cross   = (const float*)d_in[4];
    const float* w_h       = (const float*)d_in[5];
    const float* w_w       = (const float*)d_in[6];
    const float* w_d       = (const float*)d_in[7];
    float* out = (float*)d_out;

    prep_kernel<<<(NITEMS + 7) / 8, 256>>>(enc_cross, enc_h, enc_w, enc_d,
                                           w_cross, w_h, w_w, w_d);

    // Dependent launch with programmatic stream serialization (PDL).
    cudaLaunchConfig_t cfg = {};
    cfg.gridDim  = dim3(HEADS * NQ);
    cfg.blockDim = dim3(256);
    cfg.dynamicSmemBytes = 0;
    cfg.stream = 0;
    cudaLaunchAttribute attr[1];
    attr[0].id = cudaLaunchAttributeProgrammaticStreamSerialization;
    attr[0].val.programmaticStreamSerializationAllowed = 1;
    cfg.attrs = attr;
    cfg.numAttrs = 1;
    cudaLaunchKernelEx(&cfg, scores_kernel, out);
}